// round 15
// baseline (speedup 1.0000x reference)
#include <cuda_runtime.h>
#include <cuda_bf16.h>
#include <math.h>
#include <stdint.h>

#define B_    4
#define L_    4096
#define H_    1024
#define H3_   3072
#define LC_   1024
#define KSEL_ 512
#define WIN_  256
#define NW_   16
#define SCALE_ 0.125f

typedef long long ll;
typedef __nv_bfloat16 bf16;

// ---------------- scratch -----------------------------------------------------
__device__ bf16  g_xh[(size_t)B_ * L_ * H_];
__device__ bf16  g_xqkv[(size_t)B_ * L_ * H3_];       // Q|K|V fused, ld 3072
__device__ bf16  g_VT[(size_t)B_ * H_ * L_];
__device__ bf16  g_cmp[(size_t)B_ * LC_ * H_];
__device__ bf16  g_cmpqkv[(size_t)B_ * LC_ * H3_];
__device__ bf16  g_VcT[(size_t)B_ * H_ * LC_];
__device__ float g_S[(size_t)B_ * LC_ * LC_];
__device__ bf16  g_P[(size_t)B_ * LC_ * LC_];
__device__ bf16  g_comp_g[(size_t)B_ * LC_ * H_];
__device__ bf16  g_QKVs[(size_t)B_ * KSEL_ * H3_];
__device__ bf16  g_VsT[(size_t)B_ * H_ * KSEL_];
__device__ bf16  g_sel_g[(size_t)B_ * KSEL_ * H_];
__device__ bf16  g_win_g[(size_t)B_ * L_ * H_];
__device__ float g_pre[(size_t)B_ * L_ * H_];
__device__ float g_gates[(size_t)B_ * L_ * 3];
__device__ float g_scores[(size_t)B_ * L_];
__device__ int   g_idx[B_ * KSEL_];
__device__ bf16  g_Wqkv[(size_t)H3_ * H_];
__device__ bf16  g_WcT[(size_t)H_ * 4 * H_];
__device__ bf16  g_WoT[(size_t)H_ * 3 * H_];
__device__ float g_bqkv[H3_];

// ---------------- asm helpers --------------------------------------------------
__device__ __forceinline__ void mma_bf16(float& c0, float& c1, float& c2, float& c3,
                                         uint32_t a0, uint32_t a1, uint32_t a2, uint32_t a3,
                                         uint32_t b0, uint32_t b1) {
    asm volatile(
        "mma.sync.aligned.m16n8k16.row.col.f32.bf16.bf16.f32 "
        "{%0,%1,%2,%3}, {%4,%5,%6,%7}, {%8,%9}, {%0,%1,%2,%3};"
        : "+f"(c0), "+f"(c1), "+f"(c2), "+f"(c3)
        : "r"(a0), "r"(a1), "r"(a2), "r"(a3), "r"(b0), "r"(b1));
}
__device__ __forceinline__ void ldsm4(uint32_t& r0, uint32_t& r1, uint32_t& r2, uint32_t& r3,
                                      uint32_t addr) {
    asm volatile("ldmatrix.sync.aligned.m8n8.x4.shared.b16 {%0,%1,%2,%3}, [%4];"
                 : "=r"(r0), "=r"(r1), "=r"(r2), "=r"(r3) : "r"(addr));
}
__device__ __forceinline__ void cpasync16(uint32_t dst, const void* src) {
    asm volatile("cp.async.cg.shared.global [%0], [%1], 16;" :: "r"(dst), "l"(src));
}
__device__ __forceinline__ void cp_commit() { asm volatile("cp.async.commit_group;"); }
template <int N> __device__ __forceinline__ void cp_wait() {
    asm volatile("cp.async.wait_group %0;" :: "n"(N));
}

// ---------------- bf16 TC GEMM: C = alpha*A*B^T*(rowScale) + bias (+C) ----------
// A: MxK bf16 ld=lda. B: NxK bf16 ld=ldb. 256 thr, 8 warps 4x2,
// warp tile 32x64, BK=64, DOUBLE-buffered cp.async (STG=2, 73.7KB smem).
// REQUIRES M%128==0, N%128==0, K%64==0, K>=128.
#define BK_     64
#define ASTR_   72                           // bf16 units per smem row (144B)
#define TILEB_  (128 * ASTR_ * 2)            // 18432 B per tile
#define STGB_   (2 * TILEB_)                 // 36864 B per stage (A+B)
#define STG_    2
#define GEMM_SMEM (STG_ * STGB_)             // 73728 B

template <int OUT_BF, int ACC>
__global__ void __launch_bounds__(256, 2)
gemm_bf(const bf16* __restrict__ A, const bf16* __restrict__ Bm,
        const float* __restrict__ bias, const float* __restrict__ rs,
        ll rsO, ll rsI, void* __restrict__ Cv,
        int M, int N, int K, float alpha, int lda, int ldb,
        ll saO, ll saI, int innerCnt, ll sbO, ll sbI, ll sC)
{
    extern __shared__ char sm[];
    const int z = blockIdx.z;
    const bf16* Ab = A + (ll)(z / innerCnt) * saO + (ll)(z % innerCnt) * saI
                       + (ll)blockIdx.y * 128 * lda;
    const bf16* Bb = Bm + (ll)(z / innerCnt) * sbO + (ll)(z % innerCnt) * sbI
                       + (ll)blockIdx.x * 128 * ldb;

    const int tid = threadIdx.x, lane = tid & 31, warp = tid >> 5;
    const int wm = (warp & 3) * 32, wn = (warp >> 2) * 64;
    const uint32_t smemBase = (uint32_t)__cvta_generic_to_shared(sm);

    // loader: 128 rows x 64 bf16 per tile; thread -> row tid>>1, half (tid&1)*32
    const int ldRow = tid >> 1;
    const int ldCol = (tid & 1) << 5;        // bf16 units (64 bytes per half)
    const bf16* aSrc = Ab + (ll)ldRow * lda + ldCol;
    const bf16* bSrc = Bb + (ll)ldRow * ldb + ldCol;
    const uint32_t dA = smemBase + (uint32_t)(ldRow * 144 + ldCol * 2);
    const uint32_t dB = dA + (uint32_t)TILEB_;

    // ldmatrix fragment byte offsets within a stage
    const int laneRow = lane & 15;
    const int kHalf = (lane >> 4) << 3;      // 0 or 8 bf16
    uint32_t aOff[2], bOff[4];
#pragma unroll
    for (int mt = 0; mt < 2; mt++)
        aOff[mt] = (uint32_t)(((wm + mt * 16 + laneRow) * ASTR_ + kHalf) * 2);
#pragma unroll
    for (int np = 0; np < 4; np++)
        bOff[np] = (uint32_t)(TILEB_ + ((wn + np * 16 + laneRow) * ASTR_ + kHalf) * 2);

    float acc[2][8][4];
#pragma unroll
    for (int mt = 0; mt < 2; mt++)
#pragma unroll
        for (int nt = 0; nt < 8; nt++)
#pragma unroll
            for (int i = 0; i < 4; i++) acc[mt][nt][i] = 0.f;

    const int kTiles = K >> 6;

    // prologue: stage 0 into slot 0
    {
#pragma unroll
        for (int j = 0; j < 4; j++) {
            cpasync16(dA + j * 16, aSrc + j * 8);
            cpasync16(dB + j * 16, bSrc + j * 8);
        }
        cp_commit();
    }

    for (int kt = 0; kt < kTiles; kt++) {
        cp_wait<0>();
        __syncthreads();

        // issue load for stage kt+1 into the other slot (overlaps compute of kt)
        if (kt + 1 < kTiles) {
            const int s = kt + 1;
            const uint32_t so = (uint32_t)((s & 1) * STGB_);
#pragma unroll
            for (int j = 0; j < 4; j++) {
                cpasync16(dA + so + j * 16, aSrc + s * BK_ + j * 8);
                cpasync16(dB + so + j * 16, bSrc + s * BK_ + j * 8);
            }
            cp_commit();
        }

        const uint32_t slotB = smemBase + (uint32_t)((kt & 1) * STGB_);
#pragma unroll
        for (int ks = 0; ks < 4; ks++) {         // four k16 sub-steps
            const uint32_t kb = (uint32_t)(ks * 32);
            uint32_t afr[2][4], bfr[4][4];
#pragma unroll
            for (int mt = 0; mt < 2; mt++)
                ldsm4(afr[mt][0], afr[mt][1], afr[mt][2], afr[mt][3],
                      slotB + aOff[mt] + kb);
#pragma unroll
            for (int np = 0; np < 4; np++)
                ldsm4(bfr[np][0], bfr[np][1], bfr[np][2], bfr[np][3],
                      slotB + bOff[np] + kb);
#pragma unroll
            for (int mt = 0; mt < 2; mt++)
#pragma unroll
                for (int np = 0; np < 4; np++) {
                    mma_bf16(acc[mt][2 * np][0], acc[mt][2 * np][1],
                             acc[mt][2 * np][2], acc[mt][2 * np][3],
                             afr[mt][0], afr[mt][1], afr[mt][2], afr[mt][3],
                             bfr[np][0], bfr[np][2]);
                    mma_bf16(acc[mt][2 * np + 1][0], acc[mt][2 * np + 1][1],
                             acc[mt][2 * np + 1][2], acc[mt][2 * np + 1][3],
                             afr[mt][0], afr[mt][1], afr[mt][2], afr[mt][3],
                             bfr[np][1], bfr[np][3]);
                }
        }
    }

    const float* rsRow = rs ? rs + (z / innerCnt) * rsO + (z % innerCnt) * rsI : nullptr;
    const int g = lane >> 2, tg = lane & 3;
#pragma unroll
    for (int mt = 0; mt < 2; mt++) {
        const int rBase = blockIdx.y * 128 + wm + mt * 16 + g;
#pragma unroll
        for (int h = 0; h < 2; h++) {
            const int row = rBase + h * 8;
            const float scale = rsRow ? rsRow[(ll)row * 3] : 1.f;
#pragma unroll
            for (int nt = 0; nt < 8; nt++) {
                const int col = blockIdx.x * 128 + wn + nt * 8 + tg * 2;
                float2 bv = make_float2(0.f, 0.f);
                if (bias) bv = *(const float2*)&bias[col];
                float ox = alpha * acc[mt][nt][2 * h]     * scale + bv.x;
                float oy = alpha * acc[mt][nt][2 * h + 1] * scale + bv.y;
                if (OUT_BF) {
                    bf16* Cb = (bf16*)Cv + (ll)z * sC;
                    __nv_bfloat162 p;
                    p.x = __float2bfloat16_rn(ox);
                    p.y = __float2bfloat16_rn(oy);
                    *(__nv_bfloat162*)(Cb + (ll)row * N + col) = p;
                } else {
                    float* Cb = (float*)Cv + (ll)z * sC;
                    float2 o = make_float2(ox, oy);
                    if (ACC) {
                        float2 prev = *(float2*)(Cb + (ll)row * N + col);
                        o.x += prev.x; o.y += prev.y;
                    }
                    *(float2*)(Cb + (ll)row * N + col) = o;
                }
            }
        }
    }
}

// ---------------- fp32 -> bf16 convert ----------------------------------------
__global__ void cvt_kernel(const float* __restrict__ in, bf16* __restrict__ out, ll n4)
{
    const ll i = (ll)blockIdx.x * blockDim.x + threadIdx.x;
    if (i >= n4) return;
    float4 v = ((const float4*)in)[i];
    ushort4 o;
    o.x = __bfloat16_as_ushort(__float2bfloat16_rn(v.x));
    o.y = __bfloat16_as_ushort(__float2bfloat16_rn(v.y));
    o.z = __bfloat16_as_ushort(__float2bfloat16_rn(v.z));
    o.w = __bfloat16_as_ushort(__float2bfloat16_rn(v.w));
    ((ushort4*)out)[i] = o;
}

// ---------------- transpose fp32 -> bf16 (weights; out ld = R) ------------------
__global__ void transpose_cvt_kernel(const float* __restrict__ in, bf16* __restrict__ out,
                                     int R, int C)
{
    __shared__ float t[32][33];
    const int c0 = blockIdx.x * 32, r0 = blockIdx.y * 32;
#pragma unroll
    for (int i = threadIdx.y; i < 32; i += 8)
        t[i][threadIdx.x] = in[(ll)(r0 + i) * C + c0 + threadIdx.x];
    __syncthreads();
#pragma unroll
    for (int i = threadIdx.y; i < 32; i += 8)
        out[(ll)(c0 + i) * R + r0 + threadIdx.x] = __float2bfloat16_rn(t[threadIdx.x][i]);
}

// ---------------- strided bf16 transpose (batched) ------------------------------
__global__ void transpose_bf_kernel(const bf16* __restrict__ in, bf16* __restrict__ out,
                                    int ldi, int ldo, ll inZ, ll outZ)
{
    __shared__ bf16 t[32][33];
    const int z = blockIdx.z;
    const bf16* ib = in + (ll)z * inZ;
    bf16* ob = out + (ll)z * outZ;
    const int c0 = blockIdx.x * 32, r0 = blockIdx.y * 32;
#pragma unroll
    for (int i = threadIdx.y; i < 32; i += 8)
        t[i][threadIdx.x] = ib[(ll)(r0 + i) * ldi + c0 + threadIdx.x];
    __syncthreads();
#pragma unroll
    for (int i = threadIdx.y; i < 32; i += 8)
        ob[(ll)(c0 + i) * ldo + r0 + threadIdx.x] = t[threadIdx.x][i];
}

// ---------------- pack qkv bias -------------------------------------------------
__global__ void pack_bias_kernel(const float* __restrict__ bq, const float* __restrict__ bk,
                                 const float* __restrict__ bv, float* __restrict__ bqkv)
{
    const int i = blockIdx.x * 256 + threadIdx.x;
    if (i < H_)            bqkv[i] = bq[i];
    else if (i < 2 * H_)   bqkv[i] = bk[i - H_];
    else if (i < 3 * H_)   bqkv[i] = bv[i - 2 * H_];
}

// ---------------- gates + selection scores (pure fp32) -------------------------
__global__ void gates_scores_kernel(const float* __restrict__ x,
                                    const float* __restrict__ Wg, const float* __restrict__ bg,
                                    const float* __restrict__ Ws, const float* __restrict__ bs,
                                    float* __restrict__ gates, float* __restrict__ scores)
{
    const int row = blockIdx.x * (blockDim.x >> 5) + (threadIdx.x >> 5);
    const int lane = threadIdx.x & 31;
    if (row >= B_ * L_) return;
    const float* xr = x + (ll)row * H_;
    float a0 = 0.f, a1 = 0.f, a2 = 0.f, a3 = 0.f;
    for (int k = lane; k < H_; k += 32) {
        const float xv = xr[k];
        a0 += xv * Wg[k * 3 + 0];
        a1 += xv * Wg[k * 3 + 1];
        a2 += xv * Wg[k * 3 + 2];
        a3 += xv * Ws[k];
    }
#pragma unroll
    for (int o = 16; o > 0; o >>= 1) {
        a0 += __shfl_down_sync(0xffffffffu, a0, o);
        a1 += __shfl_down_sync(0xffffffffu, a1, o);
        a2 += __shfl_down_sync(0xffffffffu, a2, o);
        a3 += __shfl_down_sync(0xffffffffu, a3, o);
    }
    if (lane == 0) {
        float s0 = 1.f / (1.f + expf(-(a0 + bg[0])));
        float s1 = 1.f / (1.f + expf(-(a1 + bg[1])));
        float s2 = 1.f / (1.f + expf(-(a2 + bg[2])));
        float inv = 1.f / (s0 + s1 + s2 + 1e-6f);
        gates[row * 3 + 0] = s0 * inv;
        gates[row * 3 + 1] = s1 * inv;
        gates[row * 3 + 2] = s2 * inv;
        scores[row] = a3 + bs[0];
    }
}

// ---------------- top-512 per batch --------------------------------------------
__global__ void topk_kernel(const float* __restrict__ scores, int* __restrict__ idx_out)
{
    __shared__ float sv[L_];
    __shared__ int   si[L_];
    __shared__ int   top[KSEL_];
    const int b = blockIdx.x;
    const float* s = scores + (ll)b * L_;
    for (int i = threadIdx.x; i < L_; i += blockDim.x) { sv[i] = s[i]; si[i] = i; }
    __syncthreads();
    for (int k = 2; k <= L_; k <<= 1)
        for (int j = k >> 1; j > 0; j >>= 1) {
            for (int i = threadIdx.x; i < L_; i += blockDim.x) {
                const int ixj = i ^ j;
                if (ixj > i) {
                    const bool desc = ((i & k) == 0);
                    const float a = sv[i], c = sv[ixj];
                    const bool sw = desc ? (a < c) : (a > c);
                    if (sw) {
                        sv[i] = c; sv[ixj] = a;
                        const int t = si[i]; si[i] = si[ixj]; si[ixj] = t;
                    }
                }
            }
            __syncthreads();
        }
    for (int i = threadIdx.x; i < KSEL_; i += blockDim.x) top[i] = si[i];
    __syncthreads();
    for (int k = 2; k <= KSEL_; k <<= 1)
        for (int j = k >> 1; j > 0; j >>= 1) {
            for (int i = threadIdx.x; i < KSEL_; i += blockDim.x) {
                const int ixj = i ^ j;
                if (ixj > i) {
                    const bool asc = ((i & k) == 0);
                    const int a = top[i], c = top[ixj];
                    const bool sw = asc ? (a > c) : (a < c);
                    if (sw) { top[i] = c; top[ixj] = a; }
                }
            }
            __syncthreads();
        }
    for (int i = threadIdx.x; i < KSEL_; i += blockDim.x) idx_out[b * KSEL_ + i] = top[i];
}

// ---------------- gather selected fused rows ------------------------------------
__global__ void gather_kernel(const bf16* __restrict__ QKV, const int* __restrict__ idx,
                              bf16* __restrict__ QKVs)
{
    const int b = blockIdx.y, r = blockIdx.x;
    const int src = idx[b * KSEL_ + r];
    const uint4* s = (const uint4*)(QKV + ((ll)b * L_ + src) * H3_);
    uint4* d = (uint4*)(QKVs + ((ll)b * KSEL_ + r) * H3_);
#pragma unroll
    for (int j = 0; j < 3; j++) d[threadIdx.x + 128 * j] = s[threadIdx.x + 128 * j];
}

// ---------------- row softmax: fp32 in -> bf16 out -------------------------------
__global__ void softmax_kernel(const float* __restrict__ S, bf16* __restrict__ P, int n)
{
    const ll row = blockIdx.x;
    const float* s = S + row * (ll)n;
    bf16* p = P + row * (ll)n;
    const int tid = threadIdx.x;
    __shared__ float red[32];
    __shared__ float bc;

    float m = -1e30f;
    for (int i = tid; i < n; i += blockDim.x) m = fmaxf(m, s[i]);
#pragma unroll
    for (int o = 16; o > 0; o >>= 1) m = fmaxf(m, __shfl_xor_sync(0xffffffffu, m, o));
    if ((tid & 31) == 0) red[tid >> 5] = m;
    __syncthreads();
    if (tid == 0) {
        float mm = -1e30f;
        for (int i = 0; i < (int)(blockDim.x >> 5); i++) mm = fmaxf(mm, red[i]);
        bc = mm;
    }
    __syncthreads();
    m = bc;
    __syncthreads();

    float sum = 0.f;
    for (int i = tid; i < n; i += blockDim.x) sum += expf(s[i] - m);
#pragma unroll
    for (int o = 16; o > 0; o >>= 1) sum += __shfl_xor_sync(0xffffffffu, sum, o);
    if ((tid & 31) == 0) red[tid >> 5] = sum;
    __syncthreads();
    if (tid == 0) {
        float ss = 0.f;
        for (int i = 0; i < (int)(blockDim.x >> 5); i++) ss += red[i];
        bc = 1.f / ss;
    }
    __syncthreads();
    const float inv = bc;
    for (int i = tid; i < n; i += blockDim.x)
        p[i] = __float2bfloat16_rn(expf(s[i] - m) * inv);
}

// ---------------- residual + layernorm --------------------------------------------
__global__ void final_ln_kernel(const float* __restrict__ pre, const float* __restrict__ x,
                                float* __restrict__ out)
{
    const ll row = blockIdx.x;
    const float* p = pre + row * (ll)H_;
    const float* xr = x + row * (ll)H_;
    float* o = out + row * (ll)H_;
    const int tid = threadIdx.x;
    __shared__ float buf[H_];
    __shared__ float red[64];
    __shared__ float stats[2];

    float s = 0.f, ss = 0.f;
    for (int i = tid; i < H_; i += blockDim.x) {
        const float v = 0.5f * (p[i] + xr[i]);
        buf[i] = v;
        s += v;
        ss += v * v;
    }
#pragma unroll
    for (int o2 = 16; o2 > 0; o2 >>= 1) {
        s  += __shfl_xor_sync(0xffffffffu, s, o2);
        ss += __shfl_xor_sync(0xffffffffu, ss, o2);
    }
    if ((tid & 31) == 0) { red[tid >> 5] = s; red[32 + (tid >> 5)] = ss; }
    __syncthreads();
    if (tid == 0) {
        float ts = 0.f, tss = 0.f;
        for (int i = 0; i < (int)(blockDim.x >> 5); i++) { ts += red[i]; tss += red[32 + i]; }
        const float mean = ts / (float)H_;
        const float var = tss / (float)H_ - mean * mean;
        stats[0] = mean;
        stats[1] = rsqrtf(var + 1e-6f);
    }
    __syncthreads();
    const float mean = stats[0], inv = stats[1];
    for (int i = tid; i < H_; i += blockDim.x) o[i] = (buf[i] - mean) * inv;
}

// ------------------------------- launcher ------------------------------------------
extern "C" void kernel_launch(void* const* d_in, const int* in_sizes, int n_in,
                              void* d_out, int out_size)
{
    const float* x  = (const float*)d_in[0];
    const float* Wq = (const float*)d_in[1];
    const float* bq = (const float*)d_in[2];
    const float* Wk = (const float*)d_in[3];
    const float* bk = (const float*)d_in[4];
    const float* Wv = (const float*)d_in[5];
    const float* bv = (const float*)d_in[6];
    const float* Wo = (const float*)d_in[7];
    const float* bo = (const float*)d_in[8];
    const float* Wg = (const float*)d_in[9];
    const float* bg = (const float*)d_in[10];
    const float* Wc = (const float*)d_in[11];
    const float* bc = (const float*)d_in[12];
    const float* Ws = (const float*)d_in[13];
    const float* bs = (const float*)d_in[14];
    float* out = (float*)d_out;

    bf16 *xh, *xqkv, *VT, *cmp, *cmpqkv, *VcT, *P;
    bf16 *QKVs, *VsT, *comp_g, *sel_g, *win_g;
    bf16 *Wqkv, *WcT, *WoT;
    float *S, *pre, *gates, *scores, *bqkv;
    int* idx;
    cudaGetSymbolAddress((void**)&xh, g_xh);
    cudaGetSymbolAddress((void**)&xqkv, g_xqkv);
    cudaGetSymbolAddress((void**)&VT, g_VT);
    cudaGetSymbolAddress((void**)&cmp, g_cmp);
    cudaGetSymbolAddress((void**)&cmpqkv, g_cmpqkv);
    cudaGetSymbolAddress((void**)&VcT, g_VcT);
    cudaGetSymbolAddress((void**)&S, g_S);
    cudaGetSymbolAddress((void**)&P, g_P);
    cudaGetSymbolAddress((void**)&comp_g, g_comp_g);
    cudaGetSymbolAddress((void**)&QKVs, g_QKVs);
    cudaGetSymbolAddress((void**)&VsT, g_VsT);
    cudaGetSymbolAddress((void**)&sel_g, g_sel_g);
    cudaGetSymbolAddress((void**)&win_g, g_win_g);
    cudaGetSymbolAddress((void**)&pre, g_pre);
    cudaGetSymbolAddress((void**)&gates, g_gates);
    cudaGetSymbolAddress((void**)&scores, g_scores);
    cudaGetSymbolAddress((void**)&idx, g_idx);
    cudaGetSymbolAddress((void**)&Wqkv, g_Wqkv);
    cudaGetSymbolAddress((void**)&WcT, g_WcT);
    cudaGetSymbolAddress((void**)&WoT, g_WoT);
    cudaGetSymbolAddress((void**)&bqkv, g_bqkv);

    cudaFuncSetAttribute((const void*)gemm_bf<0, 0>, cudaFuncAttributeMaxDynamicSharedMemorySize, GEMM_SMEM);
    cudaFuncSetAttribute((const void*)gemm_bf<0, 1>, cudaFuncAttributeMaxDynamicSharedMemorySize, GEMM_SMEM);
    cudaFuncSetAttribute((const void*)gemm_bf<1, 0>, cudaFuncAttributeMaxDynamicSharedMemorySize, GEMM_SMEM);

    const int MT = B_ * L_;
    const dim3 tb(32, 8);

    gates_scores_kernel<<<MT / 8, 256>>>(x, Wg, bg, Ws, bs, gates, scores);

    cvt_kernel<<<(unsigned)(((ll)MT * H_ / 4 + 255) / 256), 256>>>(x, xh, (ll)MT * H_ / 4);
    transpose_cvt_kernel<<<dim3(H_ / 32, H_ / 32), tb>>>(Wq, Wqkv, H_, H_);
    transpose_cvt_kernel<<<dim3(H_ / 32, H_ / 32), tb>>>(Wk, Wqkv + (size_t)H_ * H_, H_, H_);
    transpose_cvt_kernel<<<dim3(H_ / 32, H_ / 32), tb>>>(Wv, Wqkv + (size_t)2 * H_ * H_, H_, H_);
    transpose_cvt_kernel<<<dim3(H_ / 32, (4 * H_) / 32), tb>>>(Wc, WcT, 4 * H_, H_);
    transpose_cvt_kernel<<<dim3(H_ / 32, (3 * H_) / 32), tb>>>(Wo, WoT, 3 * H_, H_);
    pack_bias_kernel<<<H3_ / 256, 256>>>(bq, bk, bv, bqkv);

    // fused QKV (N=3072)
    gemm_bf<1, 0><<<dim3(H3_ / 128, MT / 128, 1), 256, GEMM_SMEM>>>(
        xh, Wqkv, bqkv, nullptr, 0, 0, xqkv, MT, H3_, H_, 1.f, H_, H_, 0, 0, 1, 0, 0, 0);
    transpose_bf_kernel<<<dim3(H_ / 32, L_ / 32, B_), tb>>>(
        xqkv + 2 * H_, VT, H3_, L_, (ll)L_ * H3_, (ll)H_ * L_);

    // compressed tokens + fused comp QKV
    gemm_bf<1, 0><<<dim3(H_ / 128, (B_ * LC_) / 128, 1), 256, GEMM_SMEM>>>(
        xh, WcT, bc, nullptr, 0, 0, cmp, B_ * LC_, H_, 4 * H_, 1.f, 4 * H_, 4 * H_, 0, 0, 1, 0, 0, 0);
    gemm_bf<1, 0><<<dim3(H3_ / 128, (B_ * LC_) / 128, 1), 256, GEMM_SMEM>>>(
        cmp, Wqkv, bqkv, nullptr, 0, 0, cmpqkv, B_ * LC_, H3_, H_, 1.f, H_, H_, 0, 0, 1, 0, 0, 0);
    transpose_bf_kernel<<<dim3(H_ / 32, LC_ / 32, B_), tb>>>(
        cmpqkv + 2 * H_, VcT, H3_, LC_, (ll)LC_ * H3_, (ll)H_ * LC_);

    topk_kernel<<<B_, 512>>>(scores, idx);
    gather_kernel<<<dim3(KSEL_, B_), 128>>>(xqkv, idx, QKVs);
    transpose_bf_kernel<<<dim3(H_ / 32, KSEL_ / 32, B_), tb>>>(
        QKVs + 2 * H_, VsT, H3_, KSEL_, (ll)KSEL_ * H3_, (ll)H_ * KSEL_);

    // ---- compressed attention ----
    gemm_bf<0, 0><<<dim3(LC_ / 128, LC_ / 128, B_), 256, GEMM_SMEM>>>(
        cmpqkv, cmpqkv + H_, nullptr, nullptr, 0, 0, S, LC_, LC_, H_, SCALE_, H3_, H3_,
        (ll)LC_ * H3_, 0, 1, (ll)LC_ * H3_, 0, (ll)LC_ * LC_);
    softmax_kernel<<<B_ * LC_, 256>>>(S, P, LC_);
    gemm_bf<1, 0><<<dim3(H_ / 128, LC_ / 128, B_), 256, GEMM_SMEM>>>(
        P, VcT, nullptr, gates + 0, (ll)L_ * 3, 0, comp_g, LC_, H_, LC_, 1.f, LC_, LC_,
        (ll)LC_ * LC_, 0, 1, (ll)H_ * LC_, 0, (ll)LC_ * H_);

    // ---- selected attention ----
    gemm_bf<0, 0><<<dim3(KSEL_ / 128, KSEL_ / 128, B_), 256, GEMM_SMEM>>>(
        QKVs, QKVs + H_, nullptr, nullptr, 0, 0, S, KSEL_, KSEL_, H_, SCALE_, H3_, H3_,
        (ll)KSEL_ * H3_, 0, 1, (ll)KSEL_ * H3_, 0, (ll)KSEL_ * KSEL_);
    softmax_kernel<<<B_ * KSEL_, 256>>>(S, P, KSEL_);
    gemm_bf<1, 0><<<dim3(H_ / 128, KSEL_ / 128, B_), 256, GEMM_SMEM>>>(
        P, VsT, nullptr, gates + 1, (ll)L_ * 3, 0, sel_g, KSEL_, H_, KSEL_, 1.f, KSEL_, KSEL_,
        (ll)KSEL_ * KSEL_, 0, 1, (ll)H_ * KSEL_, 0, (ll)KSEL_ * H_);

    // ---- window attention ----
    gemm_bf<0, 0><<<dim3(WIN_ / 128, WIN_ / 128, B_ * NW_), 256, GEMM_SMEM>>>(
        xqkv, xqkv + H_, nullptr, nullptr, 0, 0, S, WIN_, WIN_, H_, SCALE_, H3_, H3_,
        (ll)L_ * H3_, (ll)128 * H3_, NW_,
        (ll)L_ * H3_, (ll)128 * H3_, (ll)WIN_ * WIN_);
    softmax_kernel<<<B_ * NW_ * WIN_, 256>>>(S, P, WIN_);
    gemm_bf<1, 0><<<dim3(H_ / 128, WIN_ / 128, B_ * NW_), 256, GEMM_SMEM>>>(
        P, VT, nullptr, gates + 2, (ll)L_ * 3, (ll)WIN_ * 3, win_g, WIN_, H_, WIN_, 1.f, WIN_, L_,
        (ll)NW_ * WIN_ * WIN_, (ll)WIN_ * WIN_, NW_,
        (ll)H_ * L_, 128, (ll)WIN_ * H_);

    // ---- split output projection ----
    gemm_bf<0, 0><<<dim3(H_ / 128, MT / 128, 1), 256, GEMM_SMEM>>>(
        win_g, WoT + 2 * H_, bo, nullptr, 0, 0, pre, MT, H_, H_, 1.f, H_, 3 * H_, 0, 0, 1, 0, 0, 0);
    gemm_bf<0, 1><<<dim3(H_ / 128, LC_ / 128, B_), 256, GEMM_SMEM>>>(
        comp_g, WoT, nullptr, nullptr, 0, 0, pre, LC_, H_, H_, 1.f, H_, 3 * H_,
        (ll)LC_ * H_, 0, 1, 0, 0, (ll)L_ * H_);
    gemm_bf<0, 1><<<dim3(H_ / 128, KSEL_ / 128, B_), 256, GEMM_SMEM>>>(
        sel_g, WoT + H_, nullptr, nullptr, 0, 0, pre, KSEL_, H_, H_, 1.f, H_, 3 * H_,
        (ll)KSEL_ * H_, 0, 1, 0, 0, (ll)L_ * H_);

    final_ln_kernel<<<MT, 256>>>(pre, x, out);
}

// round 16
// speedup vs baseline: 1.3336x; 1.3336x over previous
#include <cuda_runtime.h>
#include <cuda_bf16.h>
#include <math.h>
#include <stdint.h>

#define B_    4
#define L_    4096
#define H_    1024
#define H3_   3072
#define LC_   1024
#define KSEL_ 512
#define WIN_  256
#define NW_   16
#define SCALE_ 0.125f

typedef long long ll;
typedef __nv_bfloat16 bf16;

// S/P packing offsets (floats / bf16 elements)
#define SOFF_COMP 0ll
#define SOFF_SEL  (4ll * 1024 * 1024)
#define SOFF_WIN  (5ll * 1024 * 1024)
#define STOT_     (9ll * 1024 * 1024)

// ---------------- scratch -----------------------------------------------------
__device__ bf16  g_xh[(size_t)B_ * L_ * H_];
__device__ bf16  g_xqkv[(size_t)B_ * L_ * H3_];
__device__ bf16  g_VT[(size_t)B_ * H_ * L_];
__device__ bf16  g_cmp[(size_t)B_ * LC_ * H_];
__device__ bf16  g_cmpqkv[(size_t)B_ * LC_ * H3_];
__device__ bf16  g_VcT[(size_t)B_ * H_ * LC_];
__device__ float g_S[(size_t)STOT_];
__device__ bf16  g_P[(size_t)STOT_];
__device__ bf16  g_comp_g[(size_t)B_ * LC_ * H_];
__device__ bf16  g_QKVs[(size_t)B_ * KSEL_ * H3_];
__device__ bf16  g_VsT[(size_t)B_ * H_ * KSEL_];
__device__ bf16  g_sel_g[(size_t)B_ * KSEL_ * H_];
__device__ bf16  g_win_g[(size_t)B_ * L_ * H_];
__device__ float g_pre[(size_t)B_ * L_ * H_];
__device__ float g_gates[(size_t)B_ * L_ * 3];
__device__ float g_scores[(size_t)B_ * L_];
__device__ int   g_idx[B_ * KSEL_];
__device__ bf16  g_Wqkv[(size_t)H3_ * H_];
__device__ bf16  g_WcT[(size_t)H_ * 4 * H_];
__device__ bf16  g_WoT[(size_t)H_ * 3 * H_];
__device__ float g_bqkv[H3_];

// ---------------- asm helpers --------------------------------------------------
__device__ __forceinline__ void mma_bf16(float& c0, float& c1, float& c2, float& c3,
                                         uint32_t a0, uint32_t a1, uint32_t a2, uint32_t a3,
                                         uint32_t b0, uint32_t b1) {
    asm volatile(
        "mma.sync.aligned.m16n8k16.row.col.f32.bf16.bf16.f32 "
        "{%0,%1,%2,%3}, {%4,%5,%6,%7}, {%8,%9}, {%0,%1,%2,%3};"
        : "+f"(c0), "+f"(c1), "+f"(c2), "+f"(c3)
        : "r"(a0), "r"(a1), "r"(a2), "r"(a3), "r"(b0), "r"(b1));
}
__device__ __forceinline__ void ldsm4(uint32_t& r0, uint32_t& r1, uint32_t& r2, uint32_t& r3,
                                      uint32_t addr) {
    asm volatile("ldmatrix.sync.aligned.m8n8.x4.shared.b16 {%0,%1,%2,%3}, [%4];"
                 : "=r"(r0), "=r"(r1), "=r"(r2), "=r"(r3) : "r"(addr));
}
__device__ __forceinline__ void cpasync16(uint32_t dst, const void* src) {
    asm volatile("cp.async.cg.shared.global [%0], [%1], 16;" :: "r"(dst), "l"(src));
}
__device__ __forceinline__ void cp_commit() { asm volatile("cp.async.commit_group;"); }
template <int N> __device__ __forceinline__ void cp_wait() {
    asm volatile("cp.async.wait_group %0;" :: "n"(N));
}

// ---------------- shared GEMM body (ROUND-8 PROVEN CONFIG) ----------------------
// C = alpha*A*B^T*(rowScale) + bias (+C).  A: 128 rows of K, ld=lda (pre-offset).
// B: 128 rows of K, ld=ldb (pre-offset). Cb pre-offset to batch base.
// 256 thr, 8 warps 4x2, warp tile 32x64, BK=32, 4-stage cp.async.
#define BK_     32
#define ASTR_   40
#define TILEB_  (128 * ASTR_ * 2)
#define STGB_   (2 * TILEB_)
#define STG_    4
#define GEMM_SMEM (STG_ * STGB_)             // 81920

template <int OUT_BF, int ACC>
__device__ __forceinline__ void gemm_body(
    const bf16* __restrict__ Ab, const bf16* __restrict__ Bb,
    const float* __restrict__ bias, const float* __restrict__ rsRow,
    void* __restrict__ Cb, int N, int K, int lda, int ldb, float alpha,
    int bx, int by)
{
    extern __shared__ char sm[];
    const int tid = threadIdx.x, lane = tid & 31, warp = tid >> 5;
    const int wm = (warp & 3) * 32, wn = (warp >> 2) * 64;
    const uint32_t smemBase = (uint32_t)__cvta_generic_to_shared(sm);

    const int ldRow = tid >> 2;
    const int ldChunk = tid & 3;
    const bf16* aSrc0 = Ab + (ll)ldRow * lda + ldChunk * 8;
    const bf16* aSrc1 = Ab + (ll)(ldRow + 64) * lda + ldChunk * 8;
    const bf16* bSrc0 = Bb + (ll)ldRow * ldb + ldChunk * 8;
    const bf16* bSrc1 = Bb + (ll)(ldRow + 64) * ldb + ldChunk * 8;
    const uint32_t dA0 = smemBase + (uint32_t)(ldRow * 80 + ldChunk * 16);
    const uint32_t dA1 = dA0 + 64u * 80u;
    const uint32_t dB0 = dA0 + (uint32_t)TILEB_;
    const uint32_t dB1 = dB0 + 64u * 80u;

    const int laneRow = lane & 15;
    const int kHalf = (lane >> 4) << 3;
    uint32_t aOff[2], bOff[4];
#pragma unroll
    for (int mt = 0; mt < 2; mt++)
        aOff[mt] = (uint32_t)(((wm + mt * 16 + laneRow) * ASTR_ + kHalf) * 2);
#pragma unroll
    for (int np = 0; np < 4; np++)
        bOff[np] = (uint32_t)(TILEB_ + ((wn + np * 16 + laneRow) * ASTR_ + kHalf) * 2);

    float acc[2][8][4];
#pragma unroll
    for (int mt = 0; mt < 2; mt++)
#pragma unroll
        for (int nt = 0; nt < 8; nt++)
#pragma unroll
            for (int i = 0; i < 4; i++) acc[mt][nt][i] = 0.f;

    const int kTiles = K >> 5;

#pragma unroll
    for (int s = 0; s < STG_ - 1; s++) {
        const uint32_t so = (uint32_t)(s * STGB_);
        cpasync16(dA0 + so, aSrc0 + s * BK_);
        cpasync16(dA1 + so, aSrc1 + s * BK_);
        cpasync16(dB0 + so, bSrc0 + s * BK_);
        cpasync16(dB1 + so, bSrc1 + s * BK_);
        cp_commit();
    }

    for (int kt = 0; kt < kTiles; kt++) {
        cp_wait<STG_ - 2>();
        __syncthreads();

        if (kt + STG_ - 1 < kTiles) {
            const int s = kt + STG_ - 1;
            const uint32_t so = (uint32_t)((s & (STG_ - 1)) * STGB_);
            cpasync16(dA0 + so, aSrc0 + s * BK_);
            cpasync16(dA1 + so, aSrc1 + s * BK_);
            cpasync16(dB0 + so, bSrc0 + s * BK_);
            cpasync16(dB1 + so, bSrc1 + s * BK_);
        }
        cp_commit();

        const uint32_t slotB = smemBase + (uint32_t)((kt & (STG_ - 1)) * STGB_);
#pragma unroll
        for (int ks = 0; ks < 2; ks++) {
            const uint32_t kb = (uint32_t)(ks * 32);
            uint32_t afr[2][4], bfr[4][4];
#pragma unroll
            for (int mt = 0; mt < 2; mt++)
                ldsm4(afr[mt][0], afr[mt][1], afr[mt][2], afr[mt][3],
                      slotB + aOff[mt] + kb);
#pragma unroll
            for (int np = 0; np < 4; np++)
                ldsm4(bfr[np][0], bfr[np][1], bfr[np][2], bfr[np][3],
                      slotB + bOff[np] + kb);
#pragma unroll
            for (int mt = 0; mt < 2; mt++)
#pragma unroll
                for (int np = 0; np < 4; np++) {
                    mma_bf16(acc[mt][2 * np][0], acc[mt][2 * np][1],
                             acc[mt][2 * np][2], acc[mt][2 * np][3],
                             afr[mt][0], afr[mt][1], afr[mt][2], afr[mt][3],
                             bfr[np][0], bfr[np][2]);
                    mma_bf16(acc[mt][2 * np + 1][0], acc[mt][2 * np + 1][1],
                             acc[mt][2 * np + 1][2], acc[mt][2 * np + 1][3],
                             afr[mt][0], afr[mt][1], afr[mt][2], afr[mt][3],
                             bfr[np][1], bfr[np][3]);
                }
        }
    }

    const int g = lane >> 2, tg = lane & 3;
#pragma unroll
    for (int mt = 0; mt < 2; mt++) {
        const int rBase = by * 128 + wm + mt * 16 + g;
#pragma unroll
        for (int h = 0; h < 2; h++) {
            const int row = rBase + h * 8;
            const float scale = rsRow ? rsRow[(ll)row * 3] : 1.f;
#pragma unroll
            for (int nt = 0; nt < 8; nt++) {
                const int col = bx * 128 + wn + nt * 8 + tg * 2;
                float2 bv = make_float2(0.f, 0.f);
                if (bias) bv = *(const float2*)&bias[col];
                float ox = alpha * acc[mt][nt][2 * h]     * scale + bv.x;
                float oy = alpha * acc[mt][nt][2 * h + 1] * scale + bv.y;
                if (OUT_BF) {
                    bf16* Cb2 = (bf16*)Cb;
                    __nv_bfloat162 p;
                    p.x = __float2bfloat16_rn(ox);
                    p.y = __float2bfloat16_rn(oy);
                    *(__nv_bfloat162*)(Cb2 + (ll)row * N + col) = p;
                } else {
                    float* Cb2 = (float*)Cb;
                    float2 o = make_float2(ox, oy);
                    if (ACC) {
                        float2 prev = *(float2*)(Cb2 + (ll)row * N + col);
                        o.x += prev.x; o.y += prev.y;
                    }
                    *(float2*)(Cb2 + (ll)row * N + col) = o;
                }
            }
        }
    }
}

// ---------------- plain batched GEMM (projections / Wo) -------------------------
template <int OUT_BF, int ACC>
__global__ void __launch_bounds__(256, 2)
gemm_bf(const bf16* __restrict__ A, const bf16* __restrict__ Bm,
        const float* __restrict__ bias, const float* __restrict__ rs,
        ll rsO, ll rsI, void* __restrict__ Cv,
        int M, int N, int K, float alpha, int lda, int ldb,
        ll saO, ll saI, int innerCnt, ll sbO, ll sbI, ll sC)
{
    const int z = blockIdx.z;
    const bf16* Ab = A + (ll)(z / innerCnt) * saO + (ll)(z % innerCnt) * saI
                       + (ll)blockIdx.y * 128 * lda;
    const bf16* Bb = Bm + (ll)(z / innerCnt) * sbO + (ll)(z % innerCnt) * sbI
                       + (ll)blockIdx.x * 128 * ldb;
    const float* rsRow = rs ? rs + (z / innerCnt) * rsO + (z % innerCnt) * rsI : nullptr;
    void* Cb = (OUT_BF ? (void*)((bf16*)Cv + (ll)z * sC) : (void*)((float*)Cv + (ll)z * sC));
    gemm_body<OUT_BF, ACC>(Ab, Bb, bias, rsRow, Cb, N, K, lda, ldb, alpha,
                           blockIdx.x, blockIdx.y);
}

// ---------------- segmented GEMM (3 heterogeneous batches, one launch) ----------
struct GSeg {
    const bf16 *A, *B;
    void* C;
    const float* rs;
    ll saO, saI, sbO, sbI, sC, rsO, rsI;
    int innerCnt, N, K, lda, ldb, nx, ny, gridOff;
    float alpha;
};

template <int OUT_BF>
__global__ void __launch_bounds__(256, 2)
gemm_seg(GSeg s0, GSeg s1, GSeg s2)
{
    const int lin = blockIdx.x;
    GSeg sg = (lin < s1.gridOff) ? s0 : ((lin < s2.gridOff) ? s1 : s2);
    const int local = lin - sg.gridOff;
    const int per = sg.nx * sg.ny;
    const int z = local / per;
    const int rem = local - z * per;
    const int by = rem / sg.nx;
    const int bx = rem - by * sg.nx;

    const int zq = z / sg.innerCnt, zr = z - zq * sg.innerCnt;
    const bf16* Ab = sg.A + zq * sg.saO + zr * sg.saI + (ll)by * 128 * sg.lda;
    const bf16* Bb = sg.B + zq * sg.sbO + zr * sg.sbI + (ll)bx * 128 * sg.ldb;
    const float* rsRow = sg.rs ? sg.rs + zq * sg.rsO + zr * sg.rsI : nullptr;
    void* Cb = (OUT_BF ? (void*)((bf16*)sg.C + (ll)z * sg.sC)
                       : (void*)((float*)sg.C + (ll)z * sg.sC));
    gemm_body<OUT_BF, 0>(Ab, Bb, nullptr, rsRow, Cb, sg.N, sg.K, sg.lda, sg.ldb,
                         sg.alpha, bx, by);
}

// ---------------- fp32 -> bf16 convert ----------------------------------------
__global__ void cvt_kernel(const float* __restrict__ in, bf16* __restrict__ out, ll n4)
{
    const ll i = (ll)blockIdx.x * blockDim.x + threadIdx.x;
    if (i >= n4) return;
    float4 v = ((const float4*)in)[i];
    ushort4 o;
    o.x = __bfloat16_as_ushort(__float2bfloat16_rn(v.x));
    o.y = __bfloat16_as_ushort(__float2bfloat16_rn(v.y));
    o.z = __bfloat16_as_ushort(__float2bfloat16_rn(v.z));
    o.w = __bfloat16_as_ushort(__float2bfloat16_rn(v.w));
    ((ushort4*)out)[i] = o;
}

// ---------------- transpose fp32 -> bf16 ----------------------------------------
__global__ void transpose_cvt_kernel(const float* __restrict__ in, bf16* __restrict__ out,
                                     int R, int C)
{
    __shared__ float t[32][33];
    const int c0 = blockIdx.x * 32, r0 = blockIdx.y * 32;
#pragma unroll
    for (int i = threadIdx.y; i < 32; i += 8)
        t[i][threadIdx.x] = in[(ll)(r0 + i) * C + c0 + threadIdx.x];
    __syncthreads();
#pragma unroll
    for (int i = threadIdx.y; i < 32; i += 8)
        out[(ll)(c0 + i) * R + r0 + threadIdx.x] = __float2bfloat16_rn(t[threadIdx.x][i]);
}

// ---------------- strided bf16 transpose (batched) ------------------------------
__global__ void transpose_bf_kernel(const bf16* __restrict__ in, bf16* __restrict__ out,
                                    int ldi, int ldo, ll inZ, ll outZ)
{
    __shared__ bf16 t[32][33];
    const int z = blockIdx.z;
    const bf16* ib = in + (ll)z * inZ;
    bf16* ob = out + (ll)z * outZ;
    const int c0 = blockIdx.x * 32, r0 = blockIdx.y * 32;
#pragma unroll
    for (int i = threadIdx.y; i < 32; i += 8)
        t[i][threadIdx.x] = ib[(ll)(r0 + i) * ldi + c0 + threadIdx.x];
    __syncthreads();
#pragma unroll
    for (int i = threadIdx.y; i < 32; i += 8)
        ob[(ll)(c0 + i) * ldo + r0 + threadIdx.x] = t[threadIdx.x][i];
}

// ---------------- pack qkv bias -------------------------------------------------
__global__ void pack_bias_kernel(const float* __restrict__ bq, const float* __restrict__ bk,
                                 const float* __restrict__ bv, float* __restrict__ bqkv)
{
    const int i = blockIdx.x * 256 + threadIdx.x;
    if (i < H_)            bqkv[i] = bq[i];
    else if (i < 2 * H_)   bqkv[i] = bk[i - H_];
    else if (i < 3 * H_)   bqkv[i] = bv[i - 2 * H_];
}

// ---------------- gates + selection scores --------------------------------------
__global__ void gates_scores_kernel(const float* __restrict__ x,
                                    const float* __restrict__ Wg, const float* __restrict__ bg,
                                    const float* __restrict__ Ws, const float* __restrict__ bs,
                                    float* __restrict__ gates, float* __restrict__ scores)
{
    const int row = blockIdx.x * (blockDim.x >> 5) + (threadIdx.x >> 5);
    const int lane = threadIdx.x & 31;
    if (row >= B_ * L_) return;
    const float* xr = x + (ll)row * H_;
    float a0 = 0.f, a1 = 0.f, a2 = 0.f, a3 = 0.f;
    for (int k = lane; k < H_; k += 32) {
        const float xv = xr[k];
        a0 += xv * Wg[k * 3 + 0];
        a1 += xv * Wg[k * 3 + 1];
        a2 += xv * Wg[k * 3 + 2];
        a3 += xv * Ws[k];
    }
#pragma unroll
    for (int o = 16; o > 0; o >>= 1) {
        a0 += __shfl_down_sync(0xffffffffu, a0, o);
        a1 += __shfl_down_sync(0xffffffffu, a1, o);
        a2 += __shfl_down_sync(0xffffffffu, a2, o);
        a3 += __shfl_down_sync(0xffffffffu, a3, o);
    }
    if (lane == 0) {
        float s0 = 1.f / (1.f + expf(-(a0 + bg[0])));
        float s1 = 1.f / (1.f + expf(-(a1 + bg[1])));
        float s2 = 1.f / (1.f + expf(-(a2 + bg[2])));
        float inv = 1.f / (s0 + s1 + s2 + 1e-6f);
        gates[row * 3 + 0] = s0 * inv;
        gates[row * 3 + 1] = s1 * inv;
        gates[row * 3 + 2] = s2 * inv;
        scores[row] = a3 + bs[0];
    }
}

// ---------------- top-512 per batch --------------------------------------------
__global__ void topk_kernel(const float* __restrict__ scores, int* __restrict__ idx_out)
{
    __shared__ float sv[L_];
    __shared__ int   si[L_];
    __shared__ int   top[KSEL_];
    const int b = blockIdx.x;
    const float* s = scores + (ll)b * L_;
    for (int i = threadIdx.x; i < L_; i += blockDim.x) { sv[i] = s[i]; si[i] = i; }
    __syncthreads();
    for (int k = 2; k <= L_; k <<= 1)
        for (int j = k >> 1; j > 0; j >>= 1) {
            for (int i = threadIdx.x; i < L_; i += blockDim.x) {
                const int ixj = i ^ j;
                if (ixj > i) {
                    const bool desc = ((i & k) == 0);
                    const float a = sv[i], c = sv[ixj];
                    const bool sw = desc ? (a < c) : (a > c);
                    if (sw) {
                        sv[i] = c; sv[ixj] = a;
                        const int t = si[i]; si[i] = si[ixj]; si[ixj] = t;
                    }
                }
            }
            __syncthreads();
        }
    for (int i = threadIdx.x; i < KSEL_; i += blockDim.x) top[i] = si[i];
    __syncthreads();
    for (int k = 2; k <= KSEL_; k <<= 1)
        for (int j = k >> 1; j > 0; j >>= 1) {
            for (int i = threadIdx.x; i < KSEL_; i += blockDim.x) {
                const int ixj = i ^ j;
                if (ixj > i) {
                    const bool asc = ((i & k) == 0);
                    const int a = top[i], c = top[ixj];
                    const bool sw = asc ? (a > c) : (a < c);
                    if (sw) { top[i] = c; top[ixj] = a; }
                }
            }
            __syncthreads();
        }
    for (int i = threadIdx.x; i < KSEL_; i += blockDim.x) idx_out[b * KSEL_ + i] = top[i];
}

// ---------------- gather selected fused rows ------------------------------------
__global__ void gather_kernel(const bf16* __restrict__ QKV, const int* __restrict__ idx,
                              bf16* __restrict__ QKVs)
{
    const int b = blockIdx.y, r = blockIdx.x;
    const int src = idx[b * KSEL_ + r];
    const uint4* s = (const uint4*)(QKV + ((ll)b * L_ + src) * H3_);
    uint4* d = (uint4*)(QKVs + ((ll)b * KSEL_ + r) * H3_);
#pragma unroll
    for (int j = 0; j < 3; j++) d[threadIdx.x + 128 * j] = s[threadIdx.x + 128 * j];
}

// ---------------- segmented softmax: fp32 in -> bf16 out ------------------------
// rows: [0,4096) comp n=1024; [4096,6144) sel n=512; [6144,22528) win n=256
__global__ void softmax_seg_kernel(const float* __restrict__ S, bf16* __restrict__ P)
{
    const int r = blockIdx.x;
    ll base; int n;
    if (r < 4096)       { n = 1024; base = SOFF_COMP + (ll)r * 1024; }
    else if (r < 6144)  { n = 512;  base = SOFF_SEL + (ll)(r - 4096) * 512; }
    else                { n = 256;  base = SOFF_WIN + (ll)(r - 6144) * 256; }
    const float* s = S + base;
    bf16* p = P + base;
    const int tid = threadIdx.x;
    __shared__ float red[32];
    __shared__ float bc;

    float m = -1e30f;
    for (int i = tid; i < n; i += blockDim.x) m = fmaxf(m, s[i]);
#pragma unroll
    for (int o = 16; o > 0; o >>= 1) m = fmaxf(m, __shfl_xor_sync(0xffffffffu, m, o));
    if ((tid & 31) == 0) red[tid >> 5] = m;
    __syncthreads();
    if (tid == 0) {
        float mm = -1e30f;
        for (int i = 0; i < (int)(blockDim.x >> 5); i++) mm = fmaxf(mm, red[i]);
        bc = mm;
    }
    __syncthreads();
    m = bc;
    __syncthreads();

    float sum = 0.f;
    for (int i = tid; i < n; i += blockDim.x) sum += expf(s[i] - m);
#pragma unroll
    for (int o = 16; o > 0; o >>= 1) sum += __shfl_xor_sync(0xffffffffu, sum, o);
    if ((tid & 31) == 0) red[tid >> 5] = sum;
    __syncthreads();
    if (tid == 0) {
        float ss = 0.f;
        for (int i = 0; i < (int)(blockDim.x >> 5); i++) ss += red[i];
        bc = 1.f / ss;
    }
    __syncthreads();
    const float inv = bc;
    for (int i = tid; i < n; i += blockDim.x)
        p[i] = __float2bfloat16_rn(expf(s[i] - m) * inv);
}

// ---------------- residual + layernorm ------------------------------------------
__global__ void final_ln_kernel(const float* __restrict__ pre, const float* __restrict__ x,
                                float* __restrict__ out)
{
    const ll row = blockIdx.x;
    const float* p = pre + row * (ll)H_;
    const float* xr = x + row * (ll)H_;
    float* o = out + row * (ll)H_;
    const int tid = threadIdx.x;
    __shared__ float buf[H_];
    __shared__ float red[64];
    __shared__ float stats[2];

    float s = 0.f, ss = 0.f;
    for (int i = tid; i < H_; i += blockDim.x) {
        const float v = 0.5f * (p[i] + xr[i]);
        buf[i] = v;
        s += v;
        ss += v * v;
    }
#pragma unroll
    for (int o2 = 16; o2 > 0; o2 >>= 1) {
        s  += __shfl_xor_sync(0xffffffffu, s, o2);
        ss += __shfl_xor_sync(0xffffffffu, ss, o2);
    }
    if ((tid & 31) == 0) { red[tid >> 5] = s; red[32 + (tid >> 5)] = ss; }
    __syncthreads();
    if (tid == 0) {
        float ts = 0.f, tss = 0.f;
        for (int i = 0; i < (int)(blockDim.x >> 5); i++) { ts += red[i]; tss += red[32 + i]; }
        const float mean = ts / (float)H_;
        const float var = tss / (float)H_ - mean * mean;
        stats[0] = mean;
        stats[1] = rsqrtf(var + 1e-6f);
    }
    __syncthreads();
    const float mean = stats[0], inv = stats[1];
    for (int i = tid; i < H_; i += blockDim.x) o[i] = (buf[i] - mean) * inv;
}

// ------------------------------- launcher ----------------------------------------
extern "C" void kernel_launch(void* const* d_in, const int* in_sizes, int n_in,
                              void* d_out, int out_size)
{
    const float* x  = (const float*)d_in[0];
    const float* Wq = (const float*)d_in[1];
    const float* bq = (const float*)d_in[2];
    const float* Wk = (const float*)d_in[3];
    const float* bk = (const float*)d_in[4];
    const float* Wv = (const float*)d_in[5];
    const float* bv = (const float*)d_in[6];
    const float* Wo = (const float*)d_in[7];
    const float* bo = (const float*)d_in[8];
    const float* Wg = (const float*)d_in[9];
    const float* bg = (const float*)d_in[10];
    const float* Wc = (const float*)d_in[11];
    const float* bc = (const float*)d_in[12];
    const float* Ws = (const float*)d_in[13];
    const float* bs = (const float*)d_in[14];
    float* out = (float*)d_out;

    bf16 *xh, *xqkv, *VT, *cmp, *cmpqkv, *VcT, *P;
    bf16 *QKVs, *VsT, *comp_g, *sel_g, *win_g;
    bf16 *Wqkv, *WcT, *WoT;
    float *S, *pre, *gates, *scores, *bqkv;
    int* idx;
    cudaGetSymbolAddress((void**)&xh, g_xh);
    cudaGetSymbolAddress((void**)&xqkv, g_xqkv);
    cudaGetSymbolAddress((void**)&VT, g_VT);
    cudaGetSymbolAddress((void**)&cmp, g_cmp);
    cudaGetSymbolAddress((void**)&cmpqkv, g_cmpqkv);
    cudaGetSymbolAddress((void**)&VcT, g_VcT);
    cudaGetSymbolAddress((void**)&S, g_S);
    cudaGetSymbolAddress((void**)&P, g_P);
    cudaGetSymbolAddress((void**)&comp_g, g_comp_g);
    cudaGetSymbolAddress((void**)&QKVs, g_QKVs);
    cudaGetSymbolAddress((void**)&VsT, g_VsT);
    cudaGetSymbolAddress((void**)&sel_g, g_sel_g);
    cudaGetSymbolAddress((void**)&win_g, g_win_g);
    cudaGetSymbolAddress((void**)&pre, g_pre);
    cudaGetSymbolAddress((void**)&gates, g_gates);
    cudaGetSymbolAddress((void**)&scores, g_scores);
    cudaGetSymbolAddress((void**)&idx, g_idx);
    cudaGetSymbolAddress((void**)&Wqkv, g_Wqkv);
    cudaGetSymbolAddress((void**)&WcT, g_WcT);
    cudaGetSymbolAddress((void**)&WoT, g_WoT);
    cudaGetSymbolAddress((void**)&bqkv, g_bqkv);

    cudaFuncSetAttribute((const void*)gemm_bf<0, 0>, cudaFuncAttributeMaxDynamicSharedMemorySize, GEMM_SMEM);
    cudaFuncSetAttribute((const void*)gemm_bf<0, 1>, cudaFuncAttributeMaxDynamicSharedMemorySize, GEMM_SMEM);
    cudaFuncSetAttribute((const void*)gemm_bf<1, 0>, cudaFuncAttributeMaxDynamicSharedMemorySize, GEMM_SMEM);
    cudaFuncSetAttribute((const void*)gemm_seg<0>, cudaFuncAttributeMaxDynamicSharedMemorySize, GEMM_SMEM);
    cudaFuncSetAttribute((const void*)gemm_seg<1>, cudaFuncAttributeMaxDynamicSharedMemorySize, GEMM_SMEM);

    const int MT = B_ * L_;
    const dim3 tb(32, 8);

    gates_scores_kernel<<<MT / 8, 256>>>(x, Wg, bg, Ws, bs, gates, scores);

    cvt_kernel<<<(unsigned)(((ll)MT * H_ / 4 + 255) / 256), 256>>>(x, xh, (ll)MT * H_ / 4);
    transpose_cvt_kernel<<<dim3(H_ / 32, H_ / 32), tb>>>(Wq, Wqkv, H_, H_);
    transpose_cvt_kernel<<<dim3(H_ / 32, H_ / 32), tb>>>(Wk, Wqkv + (size_t)H_ * H_, H_, H_);
    transpose_cvt_kernel<<<dim3(H_ / 32, H_ / 32), tb>>>(Wv, Wqkv + (size_t)2 * H_ * H_, H_, H_);
    transpose_cvt_kernel<<<dim3(H_ / 32, (4 * H_) / 32), tb>>>(Wc, WcT, 4 * H_, H_);
    transpose_cvt_kernel<<<dim3(H_ / 32, (3 * H_) / 32), tb>>>(Wo, WoT, 3 * H_, H_);
    pack_bias_kernel<<<H3_ / 256, 256>>>(bq, bk, bv, bqkv);

    // fused QKV (N=3072)
    gemm_bf<1, 0><<<dim3(H3_ / 128, MT / 128, 1), 256, GEMM_SMEM>>>(
        xh, Wqkv, bqkv, nullptr, 0, 0, xqkv, MT, H3_, H_, 1.f, H_, H_, 0, 0, 1, 0, 0, 0);
    transpose_bf_kernel<<<dim3(H_ / 32, L_ / 32, B_), tb>>>(
        xqkv + 2 * H_, VT, H3_, L_, (ll)L_ * H3_, (ll)H_ * L_);

    // compressed tokens + fused comp QKV
    gemm_bf<1, 0><<<dim3(H_ / 128, (B_ * LC_) / 128, 1), 256, GEMM_SMEM>>>(
        xh, WcT, bc, nullptr, 0, 0, cmp, B_ * LC_, H_, 4 * H_, 1.f, 4 * H_, 4 * H_, 0, 0, 1, 0, 0, 0);
    gemm_bf<1, 0><<<dim3(H3_ / 128, (B_ * LC_) / 128, 1), 256, GEMM_SMEM>>>(
        cmp, Wqkv, bqkv, nullptr, 0, 0, cmpqkv, B_ * LC_, H3_, H_, 1.f, H_, H_, 0, 0, 1, 0, 0, 0);
    transpose_bf_kernel<<<dim3(H_ / 32, LC_ / 32, B_), tb>>>(
        cmpqkv + 2 * H_, VcT, H3_, LC_, (ll)LC_ * H3_, (ll)H_ * LC_);

    topk_kernel<<<B_, 512>>>(scores, idx);
    gather_kernel<<<dim3(KSEL_, B_), 128>>>(xqkv, idx, QKVs);
    transpose_bf_kernel<<<dim3(H_ / 32, KSEL_ / 32, B_), tb>>>(
        QKVs + 2 * H_, VsT, H3_, KSEL_, (ll)KSEL_ * H3_, (ll)H_ * KSEL_);

    // ======== one segmented QK launch (comp | sel | win) ========
    {
        GSeg c, s, w;
        c.A = cmpqkv; c.B = cmpqkv + H_; c.C = S + SOFF_COMP; c.rs = nullptr;
        c.saO = (ll)LC_ * H3_; c.saI = 0; c.sbO = (ll)LC_ * H3_; c.sbI = 0;
        c.sC = (ll)LC_ * LC_; c.rsO = 0; c.rsI = 0; c.innerCnt = 1;
        c.N = LC_; c.K = H_; c.lda = H3_; c.ldb = H3_;
        c.nx = 8; c.ny = 8; c.gridOff = 0; c.alpha = SCALE_;

        s.A = QKVs; s.B = QKVs + H_; s.C = S + SOFF_SEL; s.rs = nullptr;
        s.saO = (ll)KSEL_ * H3_; s.saI = 0; s.sbO = (ll)KSEL_ * H3_; s.sbI = 0;
        s.sC = (ll)KSEL_ * KSEL_; s.rsO = 0; s.rsI = 0; s.innerCnt = 1;
        s.N = KSEL_; s.K = H_; s.lda = H3_; s.ldb = H3_;
        s.nx = 4; s.ny = 4; s.gridOff = 256; s.alpha = SCALE_;

        w.A = xqkv; w.B = xqkv + H_; w.C = S + SOFF_WIN; w.rs = nullptr;
        w.saO = (ll)L_ * H3_; w.saI = (ll)128 * H3_; w.sbO = (ll)L_ * H3_; w.sbI = (ll)128 * H3_;
        w.sC = (ll)WIN_ * WIN_; w.rsO = 0; w.rsI = 0; w.innerCnt = NW_;
        w.N = WIN_; w.K = H_; w.lda = H3_; w.ldb = H3_;
        w.nx = 2; w.ny = 2; w.gridOff = 320; w.alpha = SCALE_;

        gemm_seg<0><<<576, 256, GEMM_SMEM>>>(c, s, w);
    }

    // ======== one segmented softmax launch ========
    softmax_seg_kernel<<<22528, 256>>>(S, P);

    // ======== one segmented PV launch (gated bf16 out) ========
    {
        GSeg c, s, w;
        c.A = P + SOFF_COMP; c.B = VcT; c.C = comp_g; c.rs = gates + 0;
        c.saO = (ll)LC_ * LC_; c.saI = 0; c.sbO = (ll)H_ * LC_; c.sbI = 0;
        c.sC = (ll)LC_ * H_; c.rsO = (ll)L_ * 3; c.rsI = 0; c.innerCnt = 1;
        c.N = H_; c.K = LC_; c.lda = LC_; c.ldb = LC_;
        c.nx = 8; c.ny = 8; c.gridOff = 0; c.alpha = 1.f;

        s.A = P + SOFF_SEL; s.B = VsT; s.C = sel_g; s.rs = gates + 1;
        s.saO = (ll)KSEL_ * KSEL_; s.saI = 0; s.sbO = (ll)H_ * KSEL_; s.sbI = 0;
        s.sC = (ll)KSEL_ * H_; s.rsO = (ll)L_ * 3; s.rsI = 0; s.innerCnt = 1;
        s.N = H_; s.K = KSEL_; s.lda = KSEL_; s.ldb = KSEL_;
        s.nx = 8; s.ny = 4; s.gridOff = 256; s.alpha = 1.f;

        w.A = P + SOFF_WIN; w.B = VT; w.C = win_g; w.rs = gates + 2;
        w.saO = (ll)NW_ * WIN_ * WIN_; w.saI = (ll)WIN_ * WIN_;
        w.sbO = (ll)H_ * L_; w.sbI = 128;
        w.sC = (ll)WIN_ * H_; w.rsO = (ll)L_ * 3; w.rsI = (ll)WIN_ * 3; w.innerCnt = NW_;
        w.N = H_; w.K = WIN_; w.lda = WIN_; w.ldb = L_;
        w.nx = 8; w.ny = 2; w.gridOff = 384; w.alpha = 1.f;

        gemm_seg<1><<<1408, 256, GEMM_SMEM>>>(c, s, w);
    }

    // ---- split output projection ----
    gemm_bf<0, 0><<<dim3(H_ / 128, MT / 128, 1), 256, GEMM_SMEM>>>(
        win_g, WoT + 2 * H_, bo, nullptr, 0, 0, pre, MT, H_, H_, 1.f, H_, 3 * H_, 0, 0, 1, 0, 0, 0);
    gemm_bf<0, 1><<<dim3(H_ / 128, LC_ / 128, B_), 256, GEMM_SMEM>>>(
        comp_g, WoT, nullptr, nullptr, 0, 0, pre, LC_, H_, H_, 1.f, H_, 3 * H_,
        (ll)LC_ * H_, 0, 1, 0, 0, (ll)L_ * H_);
    gemm_bf<0, 1><<<dim3(H_ / 128, KSEL_ / 128, B_), 256, GEMM_SMEM>>>(
        sel_g, WoT + H_, nullptr, nullptr, 0, 0, pre, KSEL_, H_, H_, 1.f, H_, 3 * H_,
        (ll)KSEL_ * H_, 0, 1, 0, 0, (ll)L_ * H_);

    final_ln_kernel<<<MT, 256>>>(pre, x, out);
}